// round 1
// baseline (speedup 1.0000x reference)
#include <cuda_runtime.h>

// Problem constants
#define NB       1024
#define NNODES   10
#define FIN      2048
#define FOUT     128
#define NHEADS   8
#define HIDF     128

// Scratch: emb = x @ Wp + bp, shape (NB*NNODES, FOUT) = 10240 x 128
__device__ float g_emb[NB * NNODES * FOUT];

// ---------------------------------------------------------------------------
// Kernel 1: emb = x @ Wp + bp
// GEMM M=10240, K=2048, N=128. BM=32, BN=128, BK=32, 256 threads, TM=4, TN=4.
// ---------------------------------------------------------------------------
__global__ __launch_bounds__(256) void k_emb(const float* __restrict__ x,
                                             const float* __restrict__ Wp,
                                             const float* __restrict__ bp) {
    __shared__ float As[32][33];   // [k][m], padded: conflict-free transposed store
    __shared__ float Bs[32][128];  // [k][n]

    const int tid = threadIdx.x;
    const int m0  = blockIdx.x * 32;

    // A tile load mapping: one float4 per thread (32 rows x 32 k = 256 float4)
    const int a_row  = tid >> 3;          // 0..31
    const int a_col4 = (tid & 7) << 2;    // 0,4,...,28

    // thread compute tile
    const int trow = (tid >> 5) << 2;     // 0,4,...,28
    const int tcol = (tid & 31) << 2;     // 0,4,...,124

    float acc[4][4];
#pragma unroll
    for (int i = 0; i < 4; i++)
#pragma unroll
        for (int j = 0; j < 4; j++) acc[i][j] = 0.f;

    for (int k0 = 0; k0 < FIN; k0 += 32) {
        // load A tile (transposed into smem)
        float4 av = *(const float4*)(x + (size_t)(m0 + a_row) * FIN + k0 + a_col4);
        As[a_col4 + 0][a_row] = av.x;
        As[a_col4 + 1][a_row] = av.y;
        As[a_col4 + 2][a_row] = av.z;
        As[a_col4 + 3][a_row] = av.w;
        // load B tile: 32 rows x 128 cols, 4 float4 per thread
#pragma unroll
        for (int q = 0; q < 4; q++) {
            int r = (tid >> 5) + 8 * q;   // 0..31
            *(float4*)&Bs[r][tcol] = *(const float4*)(Wp + (size_t)(k0 + r) * FOUT + tcol);
        }
        __syncthreads();

#pragma unroll
        for (int k = 0; k < 32; k++) {
            float a0 = As[k][trow + 0];
            float a1 = As[k][trow + 1];
            float a2 = As[k][trow + 2];
            float a3 = As[k][trow + 3];
            float4 bv = *(const float4*)&Bs[k][tcol];
            acc[0][0] += a0 * bv.x; acc[0][1] += a0 * bv.y; acc[0][2] += a0 * bv.z; acc[0][3] += a0 * bv.w;
            acc[1][0] += a1 * bv.x; acc[1][1] += a1 * bv.y; acc[1][2] += a1 * bv.z; acc[1][3] += a1 * bv.w;
            acc[2][0] += a2 * bv.x; acc[2][1] += a2 * bv.y; acc[2][2] += a2 * bv.z; acc[2][3] += a2 * bv.w;
            acc[3][0] += a3 * bv.x; acc[3][1] += a3 * bv.y; acc[3][2] += a3 * bv.z; acc[3][3] += a3 * bv.w;
        }
        __syncthreads();
    }

    float4 bpv = *(const float4*)(bp + tcol);
#pragma unroll
    for (int i = 0; i < 4; i++) {
        int m = m0 + trow + i;
        float4 o;
        o.x = acc[i][0] + bpv.x;
        o.y = acc[i][1] + bpv.y;
        o.z = acc[i][2] + bpv.z;
        o.w = acc[i][3] + bpv.w;
        *(float4*)(g_emb + (size_t)m * FOUT + tcol) = o;
    }
}

// ---------------------------------------------------------------------------
// Kernel 2: per (batch-group, head):
//   A[n][f] = emb[b,n] @ W1[h][0:128]   (+ b1[h])
//   C[n][f] = emb[b,n] @ W1[h][128:256]
//   S(i,k)  = sum_f leaky(A[i][f]+C[k][f]) * W2[h][f] + b2[h]
//   out[b,h,j,i] = S(i, k) with k = j + (j>=i)  <=>  write pair (i,k!=i) at j=k-(k>i)
//   out[b,h,9,:] = 0
// grid (NB/8, NHEADS), 256 threads. Each CTA re-reads W1[h] (128 KB) per item
// from L1 (fits); 8 items amortize L2 traffic.
// ---------------------------------------------------------------------------
__global__ __launch_bounds__(256) void k_pair(const float* __restrict__ W1,
                                              const float* __restrict__ b1,
                                              const float* __restrict__ W2,
                                              const float* __restrict__ b2,
                                              float* __restrict__ out) {
    __shared__ float embT[128][12];   // [c][n], row stride 48B -> 16B-aligned vec loads
    __shared__ float As[NNODES][128];
    __shared__ float Cs[NNODES][128];

    const int tid  = threadIdx.x;
    const int h    = blockIdx.y;
    const int f    = tid & 127;
    const int half = tid >> 7;        // 0: A (W1 rows 0..127), 1: C (rows 128..255)
    const int lane = tid & 31;
    const int warp = tid >> 5;

    // W1[h][half*128 + c][f], stride FOUT per c
    const float* w1p = W1 + ((size_t)h * 2 * FOUT + half * FOUT) * HIDF + f;
    const float  b1v = b1[h * HIDF + f];
    float w2v[4];
#pragma unroll
    for (int q = 0; q < 4; q++) w2v[q] = W2[h * HIDF + lane + 32 * q];
    const float b2v = b2[h];

    for (int g = 0; g < 8; g++) {
        const int b = blockIdx.x * 8 + g;

        __syncthreads();  // As/Cs reads of previous item done before reuse
        // load emb[b] (10 x 128) transposed into smem
        for (int idx = tid; idx < NNODES * 128; idx += 256) {
            int n = idx >> 7;
            int c = idx & 127;
            embT[c][n] = g_emb[((size_t)b * NNODES + n) * FOUT + c];
        }
        __syncthreads();

        // phase 1: per-thread column f of A (half=0) or C (half=1)
        float acc[NNODES];
#pragma unroll
        for (int n = 0; n < NNODES; n++) acc[n] = 0.f;

#pragma unroll 8
        for (int c = 0; c < 128; c++) {
            float  w  = w1p[(size_t)c * HIDF];
            float4 e0 = *(const float4*)&embT[c][0];
            float4 e1 = *(const float4*)&embT[c][4];
            float2 e2 = *(const float2*)&embT[c][8];
            acc[0] += e0.x * w; acc[1] += e0.y * w; acc[2] += e0.z * w; acc[3] += e0.w * w;
            acc[4] += e1.x * w; acc[5] += e1.y * w; acc[6] += e1.z * w; acc[7] += e1.w * w;
            acc[8] += e2.x * w; acc[9] += e2.y * w;
        }

        if (half == 0) {
#pragma unroll
            for (int n = 0; n < NNODES; n++) As[n][f] = acc[n] + b1v;
        } else {
#pragma unroll
            for (int n = 0; n < NNODES; n++) Cs[n][f] = acc[n];
        }
        __syncthreads();

        // phase 2: 90 off-diagonal pairs, one warp per pair
        float* outp = out + ((size_t)b * NHEADS + h) * 100;
        for (int p = warp; p < 90; p += 8) {
            int i  = p / 9;
            int kk = p - i * 9;           // output row j == kk
            int k  = kk + (kk >= i);      // source node
            float s = 0.f;
#pragma unroll
            for (int q = 0; q < 4; q++) {
                int ff = lane + 32 * q;
                float v = As[i][ff] + Cs[k][ff];
                v = (v > 0.f) ? v : 0.2f * v;
                s += v * w2v[q];
            }
#pragma unroll
            for (int off = 16; off > 0; off >>= 1)
                s += __shfl_xor_sync(0xffffffffu, s, off);
            if (lane == 0) outp[kk * 10 + i] = s + b2v;
        }
        // row 9 is never written by the scatter -> zero it
        if (tid < 10) outp[90 + tid] = 0.f;
    }
}

// ---------------------------------------------------------------------------
// Launch
// inputs: 0 object_features, 1 scene_geometry (unused), 2 Wp, 3 bp,
//         4 W1, 5 b1, 6 W2, 7 b2, 8 d_max (fixed 10)
// ---------------------------------------------------------------------------
extern "C" void kernel_launch(void* const* d_in, const int* in_sizes, int n_in,
                              void* d_out, int out_size) {
    const float* x  = (const float*)d_in[0];
    const float* Wp = (const float*)d_in[2];
    const float* bp = (const float*)d_in[3];
    const float* W1 = (const float*)d_in[4];
    const float* b1 = (const float*)d_in[5];
    const float* W2 = (const float*)d_in[6];
    const float* b2 = (const float*)d_in[7];
    float* out = (float*)d_out;

    k_emb<<<(NB * NNODES) / 32, 256>>>(x, Wp, bp);

    dim3 g2(NB / 8, NHEADS);
    k_pair<<<g2, 256>>>(W1, b1, W2, b2, out);
}

// round 2
// speedup vs baseline: 1.7425x; 1.7425x over previous
#include <cuda_runtime.h>

#define NB      1024
#define NNODES  10
#define FIN     2048
#define FOUT    128
#define NHEADS  8
#define MTOT    (NB * NNODES)   // 10240

// Scratch (allocation-guard-safe __device__ globals)
__device__ float g_emb[MTOT * FOUT];                 // 5.2 MB
__device__ float g_AC[16 * MTOT * FOUT];             // 84 MB: [z][m][f], z = 2h + half

// ---------------------------------------------------------------------------
// helpers
// ---------------------------------------------------------------------------
__device__ __forceinline__ float tf32r(float x) {
    unsigned y;
    asm("cvt.rna.tf32.f32 %0, %1;" : "=r"(y) : "f"(x));
    return __uint_as_float(y);
}
__device__ __forceinline__ float4 tf32r4(float4 v) {
    v.x = tf32r(v.x); v.y = tf32r(v.y); v.z = tf32r(v.z); v.w = tf32r(v.w);
    return v;
}
__device__ __forceinline__ void mma1688(float* c, const unsigned* a, unsigned b0, unsigned b1) {
    asm volatile(
        "mma.sync.aligned.m16n8k8.row.col.f32.tf32.tf32.f32 "
        "{%0,%1,%2,%3}, {%4,%5,%6,%7}, {%8,%9}, {%0,%1,%2,%3};"
        : "+f"(c[0]), "+f"(c[1]), "+f"(c[2]), "+f"(c[3])
        : "r"(a[0]), "r"(a[1]), "r"(a[2]), "r"(a[3]), "r"(b0), "r"(b1));
}

// ---------------------------------------------------------------------------
// TF32 MMA GEMM core: C[m0:m0+32][0:128] = A[m0:m0+32][0:K] @ B[0:K][0:128] (+bias)
// 128 threads, 4 warps, warp n-split (warptile 32x32). BK=32.
// Smem pads: As stride 36 -> a-frag bank = (4g+t) all-distinct;
//            Bs stride 136 -> b-frag bank = (8t+g) all-distinct.  Conflict-free.
// Register double-buffer: prefetch next K-chunk during compute.
// ---------------------------------------------------------------------------
template <int KTOT>
__device__ __forceinline__ void gemm_core(const float* __restrict__ Ag, int lda,
                                          const float* __restrict__ Bg,
                                          const float* __restrict__ bias,
                                          float* __restrict__ Cg, int m0) {
    __shared__ __align__(16) float As[32 * 36];
    __shared__ __align__(16) float Bs[32 * 136];

    const int tid  = threadIdx.x;
    const int lane = tid & 31;
    const int warp = tid >> 5;      // n-tile group 0..3
    const int g    = lane >> 2;     // groupID
    const int t    = lane & 3;      // threadID-in-group

    float4 pa[2], pb[8];

    auto loadAB = [&](int k0) {
#pragma unroll
        for (int i = 0; i < 2; i++) {
            int idx = tid + 128 * i;
            int m = idx >> 3, c4 = idx & 7;
            pa[i] = *(const float4*)(Ag + (size_t)(m0 + m) * lda + k0 + c4 * 4);
        }
#pragma unroll
        for (int i = 0; i < 8; i++) {
            int idx = tid + 128 * i;
            int r = idx >> 5, n4 = idx & 31;
            pb[i] = *(const float4*)(Bg + (size_t)(k0 + r) * FOUT + n4 * 4);
        }
    };
    auto stsAB = [&]() {
#pragma unroll
        for (int i = 0; i < 2; i++) {
            int idx = tid + 128 * i;
            int m = idx >> 3, c4 = idx & 7;
            *(float4*)(As + m * 36 + c4 * 4) = tf32r4(pa[i]);
        }
#pragma unroll
        for (int i = 0; i < 8; i++) {
            int idx = tid + 128 * i;
            int r = idx >> 5, n4 = idx & 31;
            *(float4*)(Bs + r * 136 + n4 * 4) = tf32r4(pb[i]);
        }
    };

    float acc[2][4][4];
#pragma unroll
    for (int mt = 0; mt < 2; mt++)
#pragma unroll
        for (int nt = 0; nt < 4; nt++)
#pragma unroll
            for (int q = 0; q < 4; q++) acc[mt][nt][q] = 0.f;

    auto compute = [&]() {
#pragma unroll
        for (int ks = 0; ks < 4; ks++) {
            unsigned a[2][4];
#pragma unroll
            for (int mt = 0; mt < 2; mt++) {
                const float* ap = As + (mt * 16 + g) * 36 + ks * 8 + t;
                a[mt][0] = __float_as_uint(ap[0]);        // (g,      t)
                a[mt][1] = __float_as_uint(ap[288]);      // (g+8,    t)     288 = 8*36
                a[mt][2] = __float_as_uint(ap[4]);        // (g,      t+4)
                a[mt][3] = __float_as_uint(ap[292]);      // (g+8,    t+4)
            }
#pragma unroll
            for (int nt = 0; nt < 4; nt++) {
                const float* bp_ = Bs + (ks * 8 + t) * 136 + warp * 32 + nt * 8 + g;
                unsigned b0 = __float_as_uint(bp_[0]);    // (k=t,   n=g)
                unsigned b1 = __float_as_uint(bp_[544]);  // (k=t+4, n=g)   544 = 4*136
#pragma unroll
                for (int mt = 0; mt < 2; mt++) mma1688(acc[mt][nt], a[mt], b0, b1);
            }
        }
    };

    loadAB(0);
    stsAB();
    __syncthreads();
    const int NCH = KTOT / 32;
    for (int ch = 1; ch < NCH; ch++) {
        loadAB(ch * 32);     // prefetch next chunk into regs
        compute();           // compute current chunk from smem
        __syncthreads();
        stsAB();
        __syncthreads();
    }
    compute();

    // epilogue: c0:(g,2t) c1:(g,2t+1) c2:(g+8,2t) c3:(g+8,2t+1)
#pragma unroll
    for (int mt = 0; mt < 2; mt++) {
#pragma unroll
        for (int nt = 0; nt < 4; nt++) {
            int col = warp * 32 + nt * 8 + 2 * t;
            float bb0 = bias ? bias[col] : 0.f;
            float bb1 = bias ? bias[col + 1] : 0.f;
            int row = m0 + mt * 16 + g;
            float2 v0 = make_float2(acc[mt][nt][0] + bb0, acc[mt][nt][1] + bb1);
            float2 v1 = make_float2(acc[mt][nt][2] + bb0, acc[mt][nt][3] + bb1);
            *(float2*)(Cg + (size_t)row * FOUT + col)       = v0;
            *(float2*)(Cg + (size_t)(row + 8) * FOUT + col) = v1;
        }
    }
}

// K1: emb = x @ Wp + bp
__global__ __launch_bounds__(128) void k_gemm_emb(const float* __restrict__ x,
                                                  const float* __restrict__ Wp,
                                                  const float* __restrict__ bp) {
    gemm_core<FIN>(x, FIN, Wp, bp, g_emb, blockIdx.x * 32);
}

// K2: for z = 2h+half:  g_AC[z] = emb @ W1[h][half*128 : half*128+128][:]  (+b1 if half==0)
__global__ __launch_bounds__(128) void k_gemm_proj(const float* __restrict__ W1,
                                                   const float* __restrict__ b1) {
    int z = blockIdx.y;
    int h = z >> 1, half = z & 1;
    const float* Bg   = W1 + (size_t)(h * 2 * FOUT + half * FOUT) * FOUT;
    const float* bias = (half == 0) ? (b1 + h * FOUT) : nullptr;
    gemm_core<FOUT>(g_emb, FOUT, Bg, bias, g_AC + (size_t)z * MTOT * FOUT, blockIdx.x * 32);
}

// ---------------------------------------------------------------------------
// K3: pair scoring.  For (b,h): S(i,k) = sum_f leaky(A[i][f]+C[k][f])*W2[h][f] + b2[h]
// out[b,h,j,i] = S(i, j+(j>=i)), row 9 zeroed.
// ---------------------------------------------------------------------------
__global__ __launch_bounds__(128) void k_pair3(const float* __restrict__ W2,
                                               const float* __restrict__ b2,
                                               float* __restrict__ out) {
    __shared__ float As[NNODES][128];
    __shared__ float Cs[NNODES][128];
    const int b = blockIdx.x, h = blockIdx.y;
    const int tid = threadIdx.x, lane = tid & 31, warp = tid >> 5;

    const float* Ap = g_AC + ((size_t)(2 * h) * MTOT + b * NNODES) * FOUT;
    const float* Cp = g_AC + ((size_t)(2 * h + 1) * MTOT + b * NNODES) * FOUT;
    for (int i = tid * 4; i < NNODES * 128; i += 128 * 4) {
        *(float4*)((float*)As + i) = *(const float4*)(Ap + i);
        *(float4*)((float*)Cs + i) = *(const float4*)(Cp + i);
    }
    float w2v[4];
#pragma unroll
    for (int q = 0; q < 4; q++) w2v[q] = W2[h * 128 + lane + 32 * q];
    const float b2v = b2[h];
    __syncthreads();

    float* outp = out + ((size_t)b * NHEADS + h) * 100;
    for (int p = warp; p < 90; p += 4) {
        int i  = p / 9;
        int kk = p - i * 9;            // output row j
        int k  = kk + (kk >= i);       // source node
        float s = 0.f;
#pragma unroll
        for (int q = 0; q < 4; q++) {
            float v = As[i][lane + 32 * q] + Cs[k][lane + 32 * q];
            v = (v > 0.f) ? v : 0.2f * v;
            s += v * w2v[q];
        }
#pragma unroll
        for (int off = 16; off; off >>= 1) s += __shfl_xor_sync(0xffffffffu, s, off);
        if (lane == 0) outp[kk * 10 + i] = s + b2v;
    }
    if (tid < 10) outp[90 + tid] = 0.f;
}

// ---------------------------------------------------------------------------
// Launch. inputs: 0 object_features, 1 scene_geometry(unused), 2 Wp, 3 bp,
//                 4 W1, 5 b1, 6 W2, 7 b2, 8 d_max
// ---------------------------------------------------------------------------
extern "C" void kernel_launch(void* const* d_in, const int* in_sizes, int n_in,
                              void* d_out, int out_size) {
    const float* x  = (const float*)d_in[0];
    const float* Wp = (const float*)d_in[2];
    const float* bp = (const float*)d_in[3];
    const float* W1 = (const float*)d_in[4];
    const float* b1 = (const float*)d_in[5];
    const float* W2 = (const float*)d_in[6];
    const float* b2 = (const float*)d_in[7];
    float* out = (float*)d_out;

    k_gemm_emb<<<MTOT / 32, 128>>>(x, Wp, bp);

    dim3 gp(MTOT / 32, 16);
    k_gemm_proj<<<gp, 128>>>(W1, b1);

    dim3 g3(NB, NHEADS);
    k_pair3<<<g3, 128>>>(W2, b2, out);
}

// round 3
// speedup vs baseline: 2.2262x; 1.2776x over previous
#include <cuda_runtime.h>

#define NB      1024
#define NNODES  10
#define FIN     2048
#define FOUT    128
#define NHEADS  8
#define MTOT    (NB * NNODES)   // 10240
#define KSPLIT  4
#define KCHUNK  (FIN / KSPLIT)  // 512

// Scratch (allocation-guard-safe __device__ globals)
__device__ float g_part[KSPLIT][MTOT * FOUT];        // 21 MB split-K partials
__device__ float g_emb[MTOT * FOUT];                 // 5.2 MB
__device__ float g_AC[16 * MTOT * FOUT];             // 84 MB: [z][m][f], z = 2h + half

// ---------------------------------------------------------------------------
// helpers
// ---------------------------------------------------------------------------
__device__ __forceinline__ float tf32r(float x) {
    unsigned y;
    asm("cvt.rna.tf32.f32 %0, %1;" : "=r"(y) : "f"(x));
    return __uint_as_float(y);
}
__device__ __forceinline__ float4 tf32r4(float4 v) {
    v.x = tf32r(v.x); v.y = tf32r(v.y); v.z = tf32r(v.z); v.w = tf32r(v.w);
    return v;
}
__device__ __forceinline__ void mma1688(float* c, const unsigned* a, unsigned b0, unsigned b1) {
    asm volatile(
        "mma.sync.aligned.m16n8k8.row.col.f32.tf32.tf32.f32 "
        "{%0,%1,%2,%3}, {%4,%5,%6,%7}, {%8,%9}, {%0,%1,%2,%3};"
        : "+f"(c[0]), "+f"(c[1]), "+f"(c[2]), "+f"(c[3])
        : "r"(a[0]), "r"(a[1]), "r"(a[2]), "r"(a[3]), "r"(b0), "r"(b1));
}

// ---------------------------------------------------------------------------
// TF32 MMA GEMM core: C[m0:m0+32][0:128] = A[m0:m0+32][k-span] @ B (+bias)
// Ag points at the first element of the CTA's k-span within row m0's row;
// Bg points at the k-span's first row. NCHUNK = k-span / 32.
// 128 threads, 4 warps, warp n-split (warptile 32x32). Conflict-free pads.
// ---------------------------------------------------------------------------
template <int NCHUNK>
__device__ __forceinline__ void gemm_core(const float* __restrict__ Ag, int lda,
                                          const float* __restrict__ Bg,
                                          const float* __restrict__ bias,
                                          float* __restrict__ Cg, int m0) {
    __shared__ __align__(16) float As[32 * 36];
    __shared__ __align__(16) float Bs[32 * 136];

    const int tid  = threadIdx.x;
    const int lane = tid & 31;
    const int warp = tid >> 5;      // n-tile group 0..3
    const int g    = lane >> 2;     // groupID
    const int t    = lane & 3;      // threadID-in-group

    float4 pa[2], pb[8];

    auto loadAB = [&](int k0) {
#pragma unroll
        for (int i = 0; i < 2; i++) {
            int idx = tid + 128 * i;
            int m = idx >> 3, c4 = idx & 7;
            pa[i] = *(const float4*)(Ag + (size_t)(m0 + m) * lda + k0 + c4 * 4);
        }
#pragma unroll
        for (int i = 0; i < 8; i++) {
            int idx = tid + 128 * i;
            int r = idx >> 5, n4 = idx & 31;
            pb[i] = *(const float4*)(Bg + (size_t)(k0 + r) * FOUT + n4 * 4);
        }
    };
    auto stsAB = [&]() {
#pragma unroll
        for (int i = 0; i < 2; i++) {
            int idx = tid + 128 * i;
            int m = idx >> 3, c4 = idx & 7;
            *(float4*)(As + m * 36 + c4 * 4) = tf32r4(pa[i]);
        }
#pragma unroll
        for (int i = 0; i < 8; i++) {
            int idx = tid + 128 * i;
            int r = idx >> 5, n4 = idx & 31;
            *(float4*)(Bs + r * 136 + n4 * 4) = tf32r4(pb[i]);
        }
    };

    float acc[2][4][4];
#pragma unroll
    for (int mt = 0; mt < 2; mt++)
#pragma unroll
        for (int nt = 0; nt < 4; nt++)
#pragma unroll
            for (int q = 0; q < 4; q++) acc[mt][nt][q] = 0.f;

    auto compute = [&]() {
#pragma unroll
        for (int ks = 0; ks < 4; ks++) {
            unsigned a[2][4];
#pragma unroll
            for (int mt = 0; mt < 2; mt++) {
                const float* ap = As + (mt * 16 + g) * 36 + ks * 8 + t;
                a[mt][0] = __float_as_uint(ap[0]);        // (g,      t)
                a[mt][1] = __float_as_uint(ap[288]);      // (g+8,    t)     288 = 8*36
                a[mt][2] = __float_as_uint(ap[4]);        // (g,      t+4)
                a[mt][3] = __float_as_uint(ap[292]);      // (g+8,    t+4)
            }
#pragma unroll
            for (int nt = 0; nt < 4; nt++) {
                const float* bp_ = Bs + (ks * 8 + t) * 136 + warp * 32 + nt * 8 + g;
                unsigned b0 = __float_as_uint(bp_[0]);    // (k=t,   n=g)
                unsigned b1 = __float_as_uint(bp_[544]);  // (k=t+4, n=g)   544 = 4*136
#pragma unroll
                for (int mt = 0; mt < 2; mt++) mma1688(acc[mt][nt], a[mt], b0, b1);
            }
        }
    };

    loadAB(0);
    stsAB();
    __syncthreads();
    for (int ch = 1; ch < NCHUNK; ch++) {
        loadAB(ch * 32);     // prefetch next chunk into regs
        compute();           // compute current chunk from smem
        __syncthreads();
        stsAB();
        __syncthreads();
    }
    compute();

    // epilogue: c0:(g,2t) c1:(g,2t+1) c2:(g+8,2t) c3:(g+8,2t+1)
#pragma unroll
    for (int mt = 0; mt < 2; mt++) {
#pragma unroll
        for (int nt = 0; nt < 4; nt++) {
            int col = warp * 32 + nt * 8 + 2 * t;
            float bb0 = bias ? bias[col] : 0.f;
            float bb1 = bias ? bias[col + 1] : 0.f;
            int row = m0 + mt * 16 + g;
            float2 v0 = make_float2(acc[mt][nt][0] + bb0, acc[mt][nt][1] + bb1);
            float2 v1 = make_float2(acc[mt][nt][2] + bb0, acc[mt][nt][3] + bb1);
            *(float2*)(Cg + (size_t)row * FOUT + col)       = v0;
            *(float2*)(Cg + (size_t)(row + 8) * FOUT + col) = v1;
        }
    }
}

// K1: split-K partials of emb = x @ Wp (+bp on split 0)
__global__ __launch_bounds__(128) void k_gemm_emb(const float* __restrict__ x,
                                                  const float* __restrict__ Wp,
                                                  const float* __restrict__ bp) {
    const int ks = blockIdx.y;
    const float* Ag   = x + (size_t)ks * KCHUNK;          // column offset into rows
    const float* Bg   = Wp + (size_t)ks * KCHUNK * FOUT;
    const float* bias = (ks == 0) ? bp : nullptr;
    gemm_core<KCHUNK / 32>(Ag, FIN, Bg, bias, g_part[ks], blockIdx.x * 32);
}

// K1b: g_emb = sum of split-K partials
__global__ __launch_bounds__(256) void k_reduce() {
    int i = (blockIdx.x * 256 + threadIdx.x) * 4;
    float4 a = *(const float4*)(g_part[0] + i);
    float4 b = *(const float4*)(g_part[1] + i);
    float4 c = *(const float4*)(g_part[2] + i);
    float4 d = *(const float4*)(g_part[3] + i);
    float4 o;
    o.x = (a.x + b.x) + (c.x + d.x);
    o.y = (a.y + b.y) + (c.y + d.y);
    o.z = (a.z + b.z) + (c.z + d.z);
    o.w = (a.w + b.w) + (c.w + d.w);
    *(float4*)(g_emb + i) = o;
}

// K2: for z = 2h+half:  g_AC[z] = emb @ W1[h][half*128 : half*128+128][:]  (+b1 if half==0)
__global__ __launch_bounds__(128) void k_gemm_proj(const float* __restrict__ W1,
                                                   const float* __restrict__ b1) {
    int z = blockIdx.y;
    int h = z >> 1, half = z & 1;
    const float* Bg   = W1 + (size_t)(h * 2 * FOUT + half * FOUT) * FOUT;
    const float* bias = (half == 0) ? (b1 + h * FOUT) : nullptr;
    gemm_core<FOUT / 32>(g_emb, FOUT, Bg, bias, g_AC + (size_t)z * MTOT * FOUT, blockIdx.x * 32);
}

// ---------------------------------------------------------------------------
// K3: pair scoring.  For (b,h): S(i,k) = sum_f leaky(A[i][f]+C[k][f])*W2[h][f] + b2[h]
// out[b,h,j,i] = S(i, j+(j>=i)), row 9 zeroed.
// ---------------------------------------------------------------------------
__global__ __launch_bounds__(128) void k_pair3(const float* __restrict__ W2,
                                               const float* __restrict__ b2,
                                               float* __restrict__ out) {
    __shared__ float As[NNODES][128];
    __shared__ float Cs[NNODES][128];
    const int b = blockIdx.x, h = blockIdx.y;
    const int tid = threadIdx.x, lane = tid & 31, warp = tid >> 5;

    const float* Ap = g_AC + ((size_t)(2 * h) * MTOT + b * NNODES) * FOUT;
    const float* Cp = g_AC + ((size_t)(2 * h + 1) * MTOT + b * NNODES) * FOUT;
    for (int i = tid * 4; i < NNODES * 128; i += 128 * 4) {
        *(float4*)((float*)As + i) = *(const float4*)(Ap + i);
        *(float4*)((float*)Cs + i) = *(const float4*)(Cp + i);
    }
    float w2v[4];
#pragma unroll
    for (int q = 0; q < 4; q++) w2v[q] = W2[h * 128 + lane + 32 * q];
    const float b2v = b2[h];
    __syncthreads();

    float* outp = out + ((size_t)b * NHEADS + h) * 100;
    for (int p = warp; p < 90; p += 4) {
        int i  = p / 9;
        int kk = p - i * 9;            // output row j
        int k  = kk + (kk >= i);       // source node
        float s = 0.f;
#pragma unroll
        for (int q = 0; q < 4; q++) {
            float v = As[i][lane + 32 * q] + Cs[k][lane + 32 * q];
            v = (v > 0.f) ? v : 0.2f * v;
            s += v * w2v[q];
        }
#pragma unroll
        for (int off = 16; off; off >>= 1) s += __shfl_xor_sync(0xffffffffu, s, off);
        if (lane == 0) outp[kk * 10 + i] = s + b2v;
    }
    if (tid < 10) outp[90 + tid] = 0.f;
}

// ---------------------------------------------------------------------------
// Launch. inputs: 0 object_features, 1 scene_geometry(unused), 2 Wp, 3 bp,
//                 4 W1, 5 b1, 6 W2, 7 b2, 8 d_max
// ---------------------------------------------------------------------------
extern "C" void kernel_launch(void* const* d_in, const int* in_sizes, int n_in,
                              void* d_out, int out_size) {
    const float* x  = (const float*)d_in[0];
    const float* Wp = (const float*)d_in[2];
    const float* bp = (const float*)d_in[3];
    const float* W1 = (const float*)d_in[4];
    const float* b1 = (const float*)d_in[5];
    const float* W2 = (const float*)d_in[6];
    const float* b2 = (const float*)d_in[7];
    float* out = (float*)d_out;

    dim3 g1(MTOT / 32, KSPLIT);
    k_gemm_emb<<<g1, 128>>>(x, Wp, bp);

    k_reduce<<<MTOT * FOUT / (256 * 4), 256>>>();

    dim3 gp(MTOT / 32, 16);
    k_gemm_proj<<<gp, 128>>>(W1, b1);

    dim3 g3(NB, NHEADS);
    k_pair3<<<g3, 128>>>(W2, b2, out);
}